// round 15
// baseline (speedup 1.0000x reference)
#include <cuda_runtime.h>
#include <cuda_bf16.h>

#define HASH_SIZE 256
#define OFFSET_SIZE 64
#define OFFSET_ENTRIES (OFFSET_SIZE * OFFSET_SIZE * OFFSET_SIZE)

// 1MB packed offset table: one uint32 per entry, f0 | f1<<8 | f2<<16.
__device__ unsigned int g_packed_offsets[OFFSET_ENTRIES];

// L2 evict-last policy — ONLY for the 1MB packed offset table.
__device__ __forceinline__ long long make_evict_last_policy() {
    long long p;
    asm("createpolicy.fractional.L2::evict_last.b64 %0, 1.0;" : "=l"(p));
    return p;
}

__device__ __forceinline__ unsigned int ldg_hint_u32(const unsigned int* ptr, long long pol) {
    unsigned int v;
    asm volatile("ld.global.L2::cache_hint.u32 %0, [%1], %2;"
                 : "=r"(v) : "l"(ptr), "l"(pol));
    return v;
}

// .cv (fetch-volatile / don't-cache) 128-bit gather: A/B to test whether the
// LTS services .cv misses at sector granularity instead of 128B line fills.
__device__ __forceinline__ float4 ldg_cv_f4(const float4* ptr) {
    float4 v;
    asm volatile("ld.global.cv.v4.f32 {%0,%1,%2,%3}, [%4];"
                 : "=f"(v.x), "=f"(v.y), "=f"(v.z), "=f"(v.w)
                 : "l"(ptr));
    return v;
}

// Prologue: pack [64^3][3] int32 -> [64^3] uint32. Each thread packs 4 entries.
__global__ __launch_bounds__(256) void pack_offsets_kernel(
    const int4* __restrict__ offset_table4)
{
    int t = blockIdx.x * blockDim.x + threadIdx.x;
    if (t >= OFFSET_ENTRIES / 4) return;

    const int4 w0 = __ldcs(&offset_table4[3 * t + 0]);
    const int4 w1 = __ldcs(&offset_table4[3 * t + 1]);
    const int4 w2 = __ldcs(&offset_table4[3 * t + 2]);

    uint4 p;
    p.x = (unsigned)((w0.x & 0xFF) | ((w0.y & 0xFF) << 8) | ((w0.z & 0xFF) << 16));
    p.y = (unsigned)((w0.w & 0xFF) | ((w1.x & 0xFF) << 8) | ((w1.y & 0xFF) << 16));
    p.z = (unsigned)((w1.z & 0xFF) | ((w1.w & 0xFF) << 8) | ((w2.x & 0xFF) << 16));
    p.w = (unsigned)((w2.y & 0xFF) | ((w2.z & 0xFF) << 8) | ((w2.w & 0xFF) << 16));

    *reinterpret_cast<uint4*>(&g_packed_offsets[4 * t]) = p;
}

__global__ __launch_bounds__(256) void psh_kernel(
    const int*    __restrict__ coords,       // [N,3] int32
    const float4* __restrict__ hash_table,   // [256,256,256,8] f32 as float4 pairs
    const float*  __restrict__ m0,           // [3]
    const float*  __restrict__ m1,           // [3]
    float4*       __restrict__ out,          // [N,8] f32 as float4 pairs
    int n)
{
    const float m0x = m0[0], m0y = m0[1], m0z = m0[2];
    const float m1x = m1[0], m1y = m1[1], m1z = m1[2];

    int i = blockIdx.x * blockDim.x + threadIdx.x;
    if (i >= n) return;

    const long long pol = make_evict_last_policy();

    // --- coords: dense, read-once -> streaming loads ---
    const int c0 = __ldcs(&coords[3 * i + 0]);
    const int c1 = __ldcs(&coords[3 * i + 1]);
    const int c2 = __ldcs(&coords[3 * i + 2]);

    // --- offset-table index: (int)(c * m1) & 63 ---
    const int o0 = ((int)((float)c0 * m1x)) & (OFFSET_SIZE - 1);
    const int o1 = ((int)((float)c1 * m1y)) & (OFFSET_SIZE - 1);
    const int o2 = ((int)((float)c2 * m1z)) & (OFFSET_SIZE - 1);
    const int oent = (((o0 << 6) | o1) << 6) | o2;

    // --- single 4B gather into the 1MB packed table (L2-resident, evict_last) ---
    const unsigned int pf = ldg_hint_u32(&g_packed_offsets[oent], pol);
    const int f0 = (int)(pf & 0xFFu);
    const int f1 = (int)((pf >> 8) & 0xFFu);
    const int f2 = (int)((pf >> 16) & 0xFFu);

    // --- hash index: ((int)(c * m0) + off) & 255 ---
    const int h0 = (((int)((float)c0 * m0x)) + f0) & (HASH_SIZE - 1);
    const int h1 = (((int)((float)c1 * m0y)) + f1) & (HASH_SIZE - 1);
    const int h2 = (((int)((float)c2 * m0z)) + f2) & (HASH_SIZE - 1);

    const long long row = (long long)((((h0 << 8) | h1) << 8) | h2) * 2;

    // --- hash gather: 32B row via .cv (A/B: sector-granular fetch?) ---
    const float4 a = ldg_cv_f4(&hash_table[row + 0]);
    const float4 b = ldg_cv_f4(&hash_table[row + 1]);

    // --- output: write-once -> streaming stores ---
    const long long ob = 2ll * i;
    __stcs(&out[ob + 0], a);
    __stcs(&out[ob + 1], b);
}

extern "C" void kernel_launch(void* const* d_in, const int* in_sizes, int n_in,
                              void* d_out, int out_size) {
    const int*    coords       = (const int*)d_in[0];
    const float4* hash_table   = (const float4*)d_in[1];
    const int4*   offset_table = (const int4*)d_in[2];
    const float*  m0           = (const float*)d_in[3];
    const float*  m1           = (const float*)d_in[4];
    float4*       out          = (float4*)d_out;

    pack_offsets_kernel<<<(OFFSET_ENTRIES / 4 + 255) / 256, 256>>>(offset_table);

    const int n = in_sizes[0] / 3;
    const int threads = 256;
    const int blocks = (n + threads - 1) / threads;
    psh_kernel<<<blocks, threads>>>(coords, hash_table, m0, m1, out, n);
}

// round 16
// speedup vs baseline: 1.4726x; 1.4726x over previous
#include <cuda_runtime.h>
#include <cuda_bf16.h>

#define HASH_SIZE 256
#define OFFSET_SIZE 64
#define OFFSET_ENTRIES (OFFSET_SIZE * OFFSET_SIZE * OFFSET_SIZE)

// 1MB packed offset table: one uint32 per entry, f0 | f1<<8 | f2<<16.
// Offsets are only used mod 256, so 8 bits per component is lossless.
__device__ unsigned int g_packed_offsets[OFFSET_ENTRIES];

// L2 evict-last policy — ONLY for the 1MB packed offset table (hot, reused).
// A/B history: evict_first/evict_last/.cv on the hash gather all regressed;
// default policy is best there.
__device__ __forceinline__ long long make_evict_last_policy() {
    long long p;
    asm("createpolicy.fractional.L2::evict_last.b64 %0, 1.0;" : "=l"(p));
    return p;
}

__device__ __forceinline__ unsigned int ldg_hint_u32(const unsigned int* ptr, long long pol) {
    unsigned int v;
    asm volatile("ld.global.L2::cache_hint.u32 %0, [%1], %2;"
                 : "=r"(v) : "l"(ptr), "l"(pol));
    return v;
}

// Single 256-bit hash-row gather with DEFAULT eviction (evict_normal):
// one L1tex request per 32B row instead of two 128-bit requests.
__device__ __forceinline__ void ldg_row_v8(const void* ptr, float4& a, float4& b) {
    asm volatile(
        "ld.global.L2::evict_normal.v8.b32 {%0,%1,%2,%3,%4,%5,%6,%7}, [%8];"
        : "=f"(a.x), "=f"(a.y), "=f"(a.z), "=f"(a.w),
          "=f"(b.x), "=f"(b.y), "=f"(b.z), "=f"(b.w)
        : "l"(ptr));
}

// Prologue: pack [64^3][3] int32 -> [64^3] uint32. Each thread packs 4 entries
// via three coalesced int4 loads -> one uint4 store.
__global__ __launch_bounds__(256) void pack_offsets_kernel(
    const int4* __restrict__ offset_table4)
{
    int t = blockIdx.x * blockDim.x + threadIdx.x;
    if (t >= OFFSET_ENTRIES / 4) return;

    const int4 w0 = __ldcs(&offset_table4[3 * t + 0]);
    const int4 w1 = __ldcs(&offset_table4[3 * t + 1]);
    const int4 w2 = __ldcs(&offset_table4[3 * t + 2]);

    uint4 p;
    p.x = (unsigned)((w0.x & 0xFF) | ((w0.y & 0xFF) << 8) | ((w0.z & 0xFF) << 16));
    p.y = (unsigned)((w0.w & 0xFF) | ((w1.x & 0xFF) << 8) | ((w1.y & 0xFF) << 16));
    p.z = (unsigned)((w1.z & 0xFF) | ((w1.w & 0xFF) << 8) | ((w2.x & 0xFF) << 16));
    p.w = (unsigned)((w2.y & 0xFF) | ((w2.z & 0xFF) << 8) | ((w2.w & 0xFF) << 16));

    *reinterpret_cast<uint4*>(&g_packed_offsets[4 * t]) = p;
}

__global__ __launch_bounds__(256) void psh_kernel(
    const int*    __restrict__ coords,       // [N,3] int32
    const float*  __restrict__ hash_table,   // [256,256,256,8] f32
    const float*  __restrict__ m0,           // [3]
    const float*  __restrict__ m1,           // [3]
    float4*       __restrict__ out,          // [N,8] f32 as float4 pairs
    int n)
{
    const float m0x = m0[0], m0y = m0[1], m0z = m0[2];
    const float m1x = m1[0], m1y = m1[1], m1z = m1[2];

    int i = blockIdx.x * blockDim.x + threadIdx.x;
    if (i >= n) return;

    const long long pol = make_evict_last_policy();

    // --- coords: dense, read-once -> streaming loads ---
    const int c0 = __ldcs(&coords[3 * i + 0]);
    const int c1 = __ldcs(&coords[3 * i + 1]);
    const int c2 = __ldcs(&coords[3 * i + 2]);

    // --- offset-table index: (int)(c * m1) & 63 (& == floor-mod for pow2) ---
    const int o0 = ((int)((float)c0 * m1x)) & (OFFSET_SIZE - 1);
    const int o1 = ((int)((float)c1 * m1y)) & (OFFSET_SIZE - 1);
    const int o2 = ((int)((float)c2 * m1z)) & (OFFSET_SIZE - 1);
    const int oent = (((o0 << 6) | o1) << 6) | o2;

    // --- single 4B gather into the 1MB packed table (L2-resident, evict_last) ---
    const unsigned int pf = ldg_hint_u32(&g_packed_offsets[oent], pol);
    const int f0 = (int)(pf & 0xFFu);
    const int f1 = (int)((pf >> 8) & 0xFFu);
    const int f2 = (int)((pf >> 16) & 0xFFu);

    // --- hash index: ((int)(c * m0) + off) & 255 ---
    const int h0 = (((int)((float)c0 * m0x)) + f0) & (HASH_SIZE - 1);
    const int h1 = (((int)((float)c1 * m0y)) + f1) & (HASH_SIZE - 1);
    const int h2 = (((int)((float)c2 * m0z)) + f2) & (HASH_SIZE - 1);

    const long long row = (long long)((((h0 << 8) | h1) << 8) | h2);

    // --- hash gather: one 256-bit request, default eviction (best policy) ---
    float4 a, b;
    ldg_row_v8((const char*)hash_table + row * 32, a, b);

    // --- output: write-once -> streaming stores ---
    const long long ob = 2ll * i;
    __stcs(&out[ob + 0], a);
    __stcs(&out[ob + 1], b);
}

extern "C" void kernel_launch(void* const* d_in, const int* in_sizes, int n_in,
                              void* d_out, int out_size) {
    const int*   coords       = (const int*)d_in[0];
    const float* hash_table   = (const float*)d_in[1];
    const int4*  offset_table = (const int4*)d_in[2];
    const float* m0           = (const float*)d_in[3];
    const float* m1           = (const float*)d_in[4];
    float4*      out          = (float4*)d_out;

    pack_offsets_kernel<<<(OFFSET_ENTRIES / 4 + 255) / 256, 256>>>(offset_table);

    const int n = in_sizes[0] / 3;
    const int threads = 256;
    const int blocks = (n + threads - 1) / threads;
    psh_kernel<<<blocks, threads>>>(coords, hash_table, m0, m1, out, n);
}